// round 8
// baseline (speedup 1.0000x reference)
#include <cuda_runtime.h>
#include <cstdint>

#define NB 1024
#define NL 4096
#define NT 512
#define NWARP (NT / 32)   // 16
#define NCHUNK 2          // elements: k*2048 + 4t + j,  k in {0,1}, j in {0..3}
// 2*log2(e)/tau and ln(2)
#define K2F  3.3945765667975607f
#define LN2F 0.6931471805599453f

__device__ float g_row[NB];
__device__ unsigned g_count = 0;   // self-resetting via atomicInc wraparound

__device__ __forceinline__ float ex2f(float x) {
    float r;
    asm("ex2.approx.f32 %0, %1;" : "=f"(r) : "f"(x));
    return r;
}

__device__ __forceinline__ uint32_t smem_u32(const void* p) {
    return (uint32_t)__cvta_generic_to_shared(p);
}

__device__ __forceinline__ void mbar_init(uint32_t mbar, uint32_t cnt) {
    asm volatile("mbarrier.init.shared.b64 [%0], %1;" :: "r"(mbar), "r"(cnt) : "memory");
}
__device__ __forceinline__ void mbar_expect_tx(uint32_t mbar, uint32_t bytes) {
    asm volatile("mbarrier.arrive.expect_tx.shared.b64 _, [%0], %1;" :: "r"(mbar), "r"(bytes) : "memory");
}
__device__ __forceinline__ void bulk_g2s(uint32_t dst, const void* src, uint32_t bytes, uint32_t mbar) {
    asm volatile("cp.async.bulk.shared::cta.global.mbarrier::complete_tx::bytes [%0], [%1], %2, [%3];"
                 :: "r"(dst), "l"(src), "r"(bytes), "r"(mbar) : "memory");
}
__device__ __forceinline__ void mbar_wait(uint32_t mbar) {
    uint32_t done;
    do {
        asm volatile("{\n\t.reg .pred p;\n\t"
                     "mbarrier.try_wait.parity.acquire.cta.shared::cta.b64 p, [%1], %2, 0x989680;\n\t"
                     "selp.b32 %0, 1, 0, p;\n\t}"
                     : "=r"(done) : "r"(mbar), "r"(0u) : "memory");
    } while (!done);
}

__global__ __launch_bounds__(NT)
void fused_kernel(const float* __restrict__ probs, const int* __restrict__ labels,
                  float* __restrict__ d_out) {
    __shared__ alignas(128) int   s_lab[NL];
    __shared__ alignas(128) float s_prob[NL];
    __shared__ alignas(8)  unsigned long long s_mbar[2];
    __shared__ int   ws[NCHUNK * NWARP];     // 32 warp-chunk partial sums, global order k*16+w
    __shared__ int   woff[NCHUNK * NWARP + 1];
    __shared__ float sS[NWARP], sW[NWARP];
    __shared__ int   s_last;

    const int row  = blockIdx.x;
    const int t    = threadIdx.x;
    const int lane = t & 31;
    const int warp = t >> 5;

    const uint32_t mb0 = smem_u32(&s_mbar[0]);
    const uint32_t mb1 = smem_u32(&s_mbar[1]);
    const uint32_t lab_s  = smem_u32(s_lab);
    const uint32_t prob_s = smem_u32(s_prob);

    if (t == 0) {
        mbar_init(mb0, 1);
        mbar_init(mb1, 1);
        asm volatile("fence.proxy.async.shared::cta;" ::: "memory");
    }
    __syncthreads();
    if (t == 0) {
        mbar_expect_tx(mb0, NL * 4);
        bulk_g2s(lab_s,  labels + (size_t)row * NL, NL * 4, mb0);
        mbar_expect_tx(mb1, NL * 4);
        bulk_g2s(prob_s, probs  + (size_t)row * NL, NL * 4, mb1);
    }

    // ---- wait labels, pass 1: per-chunk sums + block scan (probs still in flight) ----
    mbar_wait(mb0);

    const int4* lab4 = reinterpret_cast<const int4*>(s_lab);
    int4 a0 = lab4[t];            // elements 4t .. 4t+3          (chunk 0)
    int4 a1 = lab4[NT + t];       // elements 2048 + 4t .. 4t+3   (chunk 1)

    int s0 = a0.x + a0.y + a0.z + a0.w;
    int s1 = a1.x + a1.y + a1.z + a1.w;

    int inc0 = s0, inc1 = s1;
#pragma unroll
    for (int d = 1; d < 32; d <<= 1) {
        int n0 = __shfl_up_sync(0xffffffffu, inc0, d);
        int n1 = __shfl_up_sync(0xffffffffu, inc1, d);
        if (lane >= d) { inc0 += n0; inc1 += n1; }
    }
    if (lane == 31) { ws[warp] = inc0; ws[NWARP + warp] = inc1; }
    __syncthreads();

    if (warp == 0) {                       // scan the 32 warp-chunk partials in global order
        int val = ws[lane];
        int inc = val;
#pragma unroll
        for (int d = 1; d < 32; d <<= 1) {
            int n = __shfl_up_sync(0xffffffffu, inc, d);
            if (lane >= d) inc += n;
        }
        woff[lane] = inc - val;            // exclusive
        if (lane == 31) woff[32] = inc;    // T = row total
    }
    __syncthreads();

    const int T    = woff[32];
    const int pre0 = woff[warp] + (inc0 - s0);
    const int pre1 = woff[NWARP + warp] + (inc1 - s1);

    // ---- wait probs, pass 2: compute ----
    mbar_wait(mb1);
    const float4* pr4 = reinterpret_cast<const float4*>(s_prob);
    float4 p0 = pr4[t];
    float4 p1 = pr4[NT + t];

    float S = 0.0f, W = 0.0f;              // W in log2 units
#pragma unroll
    for (int k = 0; k < NCHUNK; k++) {
        const int4   a = (k == 0) ? a0 : a1;
        const float4 p = (k == 0) ? p0 : p1;
        const int kbase = k * (NL / NCHUNK) + 4 * t + 1 + T;   // (idx + 1 + T) at j=0
        const float r0  = __fdividef(1.0f, (float)kbase);       // one MUFU.RCP per chunk
        const float kr0 = K2F * r0;                             // folds 2*log2(e)/tau
        float cf = (float)((k == 0) ? pre0 : pre1);
        const int   v[4] = {a.x, a.y, a.z, a.w};
        const float q[4] = {p.x, p.y, p.z, p.w};
#pragma unroll
        for (int j = 0; j < 4; j++) {
            const float tj = (float)j * r0;
            const float u  = __fmaf_rn(tj, tj, 1.0f - tj);      // 1/(kbase+j) ~= r0*(1-t+t^2)
            cf += v[j] ? 1.0f : 0.0f;
            const float f  = (cf * kr0) * u;                    // (r/tau)*log2e; 0 when c==0
            const float e  = ex2f(f);
            const float df = f - __log2f(q[j]);
            S += e;
            W = __fmaf_rn(e, df, W);
        }
    }

    // ---- block reduce (S, W) ----
#pragma unroll
    for (int d = 16; d; d >>= 1) {
        S += __shfl_down_sync(0xffffffffu, S, d);
        W += __shfl_down_sync(0xffffffffu, W, d);
    }
    if (lane == 0) { sS[warp] = S; sW[warp] = W; }
    __syncthreads();
    if (t == 0) {
        float St = 0.0f, Wt = 0.0f;
#pragma unroll
        for (int w = 0; w < NWARP; w++) { St += sS[w]; Wt += sW[w]; }
        g_row[row] = LN2F * (Wt / St) - __logf(St);   // ln2*(W/S) - ln(S)
        __threadfence();
        unsigned ticket = atomicInc(&g_count, NB - 1);
        s_last = (ticket == NB - 1);
    }
    __syncthreads();

    // ---- last-arriving CTA reduces all rows (fixed order, deterministic) ----
    if (s_last) {
        __threadfence();
        const volatile float* gr = g_row;
        float acc = 0.0f;
#pragma unroll
        for (int i = 0; i < NB / NT; i++) acc += gr[t + i * NT];
#pragma unroll
        for (int d = 16; d; d >>= 1) acc += __shfl_down_sync(0xffffffffu, acc, d);
        __shared__ float sm2[NWARP];
        if (lane == 0) sm2[warp] = acc;
        __syncthreads();
        if (t == 0) {
            float tot = 0.0f;
#pragma unroll
            for (int w = 0; w < NWARP; w++) tot += sm2[w];
            d_out[0] = tot * (1.0f / (float)NB);
        }
    }
}

extern "C" void kernel_launch(void* const* d_in, const int* in_sizes, int n_in,
                              void* d_out, int out_size) {
    const float* probs  = (const float*)d_in[0];   // output: (B, L, 1) f32
    const int*   labels = (const int*)d_in[1];     // labels: (B, L) i32
    fused_kernel<<<NB, NT>>>(probs, labels, (float*)d_out);
}